// round 2
// baseline (speedup 1.0000x reference)
#include <cuda_runtime.h>

#define KNB 16

__device__ __align__(256) float g_fA[20096 * 128];
__device__ __align__(256) float g_fB[20096 * 128];

__device__ __forceinline__ float sigf(float x) {
    return __fdividef(1.0f, 1.0f + __expf(-x));
}
__device__ __forceinline__ float tanhfast(float x) {
    return __fdividef(2.0f, 1.0f + __expf(-2.0f * x)) - 1.0f;
}
__device__ __forceinline__ float dot4(float4 a, float4 b, float acc) {
    acc = fmaf(a.x, b.x, acc);
    acc = fmaf(a.y, b.y, acc);
    acc = fmaf(a.z, b.z, acc);
    return fmaf(a.w, b.w, acc);
}

__global__ void build_feat0(const float* __restrict__ p, float* __restrict__ f0, int nN) {
    int i = blockIdx.x * blockDim.x + threadIdx.x;
    if (i >= nN * 64) return;
    int node = i >> 6, k = i & 63;
    f0[i] = (k == 0) ? (16.0f / (float)nN) : p[node * 63 + (k - 1)];
}

// One GraphSAGE-LSTM layer. CTA: 144 nodes, 256 threads.
// thread (g=tid&15, ul=tid>>4) owns nodes g+16i (i<9), hidden unit ci*16+ul per chunk.
template <int DIN, int DOUT, bool RELU>
__global__ __launch_bounds__(256, 1)
void layer_k(const float* __restrict__ fin, const int* __restrict__ nidx,
             const float* __restrict__ Wih, const float* __restrict__ Whh,
             const float* __restrict__ bih, const float* __restrict__ bhh,
             const float* __restrict__ Wself, const float* __restrict__ Wneigh,
             const float* __restrict__ bo, float* __restrict__ fout, int nN)
{
    constexpr int TM = 144, NT = 256, NCH = DIN / 16, D4 = DIN / 4, P = 2 * D4 + 1;
    extern __shared__ float sm[];
    float4* XH = (float4*)sm;          // TM rows x P float4: [x(D4) | h(D4) | pad]
    float4* WC = XH + TM * P;          // 64 rows x P float4: [Wa_row(D4) | Wb_row(D4) | pad]
    float*  BS = (float*)(WC + 64 * P);

    const int tid = threadIdx.x, g = tid & 15, ul = tid >> 4;
    const int node0 = blockIdx.x * TM;
    const float4* fin4 = (const float4*)fin;
    const float4* Wih4 = (const float4*)Wih;
    const float4* Whh4 = (const float4*)Whh;
    const float4* Wsf4 = (const float4*)Wself;
    const float4* Wng4 = (const float4*)Wneigh;

    const float4* xrow[9];
#pragma unroll
    for (int i = 0; i < 9; i++) xrow[i] = XH + (g + 16 * i) * P;

    // init h = 0, combined LSTM bias
    for (int e = tid; e < TM * D4; e += NT)
        XH[(e / D4) * P + D4 + (e % D4)] = make_float4(0.f, 0.f, 0.f, 0.f);
    for (int e = tid; e < 4 * DIN; e += NT) BS[e] = bih[e] + bhh[e];

    float c_[NCH][9], h_[NCH][9];
#pragma unroll 1
    for (int ci = 0; ci < NCH; ci++)
#pragma unroll
        for (int i = 0; i < 9; i++) { c_[ci][i] = 0.f; h_[ci][i] = 0.f; }

    for (int t = 0; t < KNB; t++) {
        __syncthreads();  // prior reads of XH done
        // gather step-t neighbor features into x-part
        for (int e = tid; e < TM * D4; e += NT) {
            int n = e / D4, k = e % D4;
            int nd = node0 + n; if (nd >= nN) nd = nN - 1;
            int src = nidx[nd * KNB + t];
            XH[n * P + k] = fin4[src * D4 + k];
        }
#pragma unroll 1
        for (int ci = 0; ci < NCH; ci++) {
            __syncthreads();  // WC reads done (and gather visible at ci=0)
            for (int e = tid; e < 64 * 2 * D4; e += NT) {
                int r = e / (2 * D4), k = e % (2 * D4);
                int gr = (r >> 4) * DIN + ci * 16 + (r & 15);
                WC[r * P + k] = (k < D4) ? Wih4[gr * D4 + k] : Whh4[gr * D4 + k - D4];
            }
            __syncthreads();
            const int u = ci * 16 + ul;
            float a0[9], a1[9], a2[9], a3[9];
            {
                float b0 = BS[u], b1 = BS[DIN + u], b2 = BS[2 * DIN + u], b3 = BS[3 * DIN + u];
#pragma unroll
                for (int i = 0; i < 9; i++) { a0[i] = b0; a1[i] = b1; a2[i] = b2; a3[i] = b3; }
            }
            const float4* w0 = WC + (ul) * P;
            const float4* w1 = WC + (16 + ul) * P;
            const float4* w2 = WC + (32 + ul) * P;
            const float4* w3 = WC + (48 + ul) * P;
#pragma unroll 2
            for (int k = 0; k < 2 * D4; k++) {
                float4 v0 = w0[k], v1 = w1[k], v2 = w2[k], v3 = w3[k];
#pragma unroll
                for (int i = 0; i < 9; i++) {
                    float4 x = xrow[i][k];
                    a0[i] = dot4(x, v0, a0[i]);
                    a1[i] = dot4(x, v1, a1[i]);
                    a2[i] = dot4(x, v2, a2[i]);
                    a3[i] = dot4(x, v3, a3[i]);
                }
            }
#pragma unroll
            for (int i = 0; i < 9; i++) {
                float cc = sigf(a1[i]) * c_[ci][i] + sigf(a0[i]) * tanhfast(a2[i]);
                c_[ci][i] = cc;
                h_[ci][i] = sigf(a3[i]) * tanhfast(cc);
            }
        }
        __syncthreads();  // all XH reads done before h update
        float* XHs = (float*)XH;
#pragma unroll 1
        for (int ci = 0; ci < NCH; ci++) {
            int u = ci * 16 + ul;
#pragma unroll
            for (int i = 0; i < 9; i++)
                XHs[(g + 16 * i) * (P * 4) + D4 * 4 + u] = h_[ci][i];
        }
    }

    // ---- FC epilogue: out = self_feat @ Wself^T + h @ Wneigh^T + b ----
    __syncthreads();
    for (int e = tid; e < TM * D4; e += NT) {  // overwrite x-part with self feature
        int n = e / D4, k = e % D4;
        int nd = node0 + n; if (nd >= nN) nd = nN - 1;
        XH[n * P + k] = fin4[nd * D4 + k];
    }
    for (int ub = 0; ub < DOUT; ub += 64) {
        __syncthreads();
        for (int e = tid; e < 64 * 2 * D4; e += NT) {
            int r = e / (2 * D4), k = e % (2 * D4);
            int u = ub + r;
            if (u < DOUT)
                WC[r * P + k] = (k < D4) ? Wsf4[u * D4 + k] : Wng4[u * D4 + k - D4];
        }
        __syncthreads();
#pragma unroll
        for (int q = 0; q < 4; q++) {
            int u = ub + q * 16 + ul;
            float acc[9];
            float bb = (u < DOUT) ? bo[u] : 0.f;
#pragma unroll
            for (int i = 0; i < 9; i++) acc[i] = bb;
            const float4* wr = WC + (q * 16 + ul) * P;
#pragma unroll 2
            for (int k = 0; k < 2 * D4; k++) {
                float4 w = wr[k];
#pragma unroll
                for (int i = 0; i < 9; i++) acc[i] = dot4(xrow[i][k], w, acc[i]);
            }
            if (u < DOUT) {
#pragma unroll
                for (int i = 0; i < 9; i++) {
                    int nd = node0 + g + 16 * i;
                    if (nd < nN) {
                        float v = acc[i];
                        if (RELU) v = fmaxf(v, 0.f);
                        fout[nd * DOUT + u] = v;
                    }
                }
            }
        }
    }
}

static int smem_bytes(int DIN) {
    int D4 = DIN / 4, P = 2 * D4 + 1;
    return (144 * P + 64 * P) * 16 + 4 * DIN * 4;
}

extern "C" void kernel_launch(void* const* d_in, const int* in_sizes, int n_in,
                              void* d_out, int out_size) {
    const float* p    = (const float*)d_in[0];
    const int*   nidx = (const int*)d_in[1];
    int nN = in_sizes[1] / KNB;

    float *fA, *fB;
    cudaGetSymbolAddress((void**)&fA, g_fA);
    cudaGetSymbolAddress((void**)&fB, g_fB);

    int sm64 = smem_bytes(64), sm128 = smem_bytes(128);
    cudaFuncSetAttribute(layer_k<64, 128, true>,  cudaFuncAttributeMaxDynamicSharedMemorySize, sm64);
    cudaFuncSetAttribute(layer_k<128, 128, true>, cudaFuncAttributeMaxDynamicSharedMemorySize, sm128);
    cudaFuncSetAttribute(layer_k<128, 32, false>, cudaFuncAttributeMaxDynamicSharedMemorySize, sm128);

    build_feat0<<<(nN * 64 + 255) / 256, 256>>>(p, fA, nN);

    int grid = (nN + 143) / 144;
    layer_k<64, 128, true><<<grid, 256, sm64>>>(
        fA, nidx,
        (const float*)d_in[2], (const float*)d_in[3], (const float*)d_in[4],
        (const float*)d_in[5], (const float*)d_in[6], (const float*)d_in[7],
        (const float*)d_in[8], fB, nN);
    layer_k<128, 128, true><<<grid, 256, sm128>>>(
        fB, nidx,
        (const float*)d_in[9], (const float*)d_in[10], (const float*)d_in[11],
        (const float*)d_in[12], (const float*)d_in[13], (const float*)d_in[14],
        (const float*)d_in[15], fA, nN);
    layer_k<128, 32, false><<<grid, 256, sm128>>>(
        fA, nidx,
        (const float*)d_in[16], (const float*)d_in[17], (const float*)d_in[18],
        (const float*)d_in[19], (const float*)d_in[20], (const float*)d_in[21],
        (const float*)d_in[22], (float*)d_out, nN);
}